// round 3
// baseline (speedup 1.0000x reference)
#include <cuda_runtime.h>
#include <cstdint>

// Batched 8-qubit circuit expectation, fully closed-form. (math verified R1)
//
//   c1 = rsqrt(1+x^2), c2 = rsqrt(1+x^4)
//   Sr = sum(w_re), Si = sum(w_im)
//   out = 0.5*cosh(Si) + 0.5*cos(Sr)*Q - 0.5*sin(Sr)*W - 0.5*sinh(Si)*Xim
//   Q   = prod_{q=1..7} c1_q
//   W   = (x0 c1_0 c2_0) * (x1 c1_1 c2_1)
//   Xim = -(x0 c1_0 c2_0) * (x1^3 c1_1 c2_1) * prod_{q=2..7} c1_q
//
// R3 change: latency-bound at MLP=2/warp with per-row overhead dominating.
// Now 4 rows per thread: 8 front-loaded LDG.128 (MLP=8), prologue/addressing
// amortized 4x, one STG.128 per thread.

#define ROWS_PER_THREAD 4

__device__ __forceinline__ float row_result(float4 v0, float4 v1,
                                            float K0, float K1, float K2, float K3)
{
    float xs[8] = {v0.x, v0.y, v0.z, v0.w, v1.x, v1.y, v1.z, v1.w};
    float c1[8];
#pragma unroll
    for (int q = 0; q < 8; ++q)
        c1[q] = rsqrtf(fmaf(xs[q], xs[q], 1.0f));

    float x0 = xs[0], x1 = xs[1];
    float x0s = x0 * x0, x1s = x1 * x1;
    float c2_0 = rsqrtf(fmaf(x0s, x0s, 1.0f));
    float c2_1 = rsqrtf(fmaf(x1s, x1s, 1.0f));

    float prod27 = (c1[2] * c1[3]) * (c1[4] * c1[5]) * (c1[6] * c1[7]);
    float Q = c1[1] * prod27;

    float tR0 = x0 * c1[0] * c2_0;
    float tR1 = x1 * c1[1] * c2_1;

    float W   = tR0 * tR1;
    float Xim = -tR0 * (x1s * tR1) * prod27;

    return fmaf(K1, Q, fmaf(K2, W, fmaf(K3, Xim, K0)));
}

__global__ __launch_bounds__(128)
void qc_expect_kernel(const float4* __restrict__ x4,
                      const float* __restrict__ wre,
                      const float* __restrict__ wim,
                      float4* __restrict__ out4,
                      int nthreads)
{
    int t = blockIdx.x * blockDim.x + threadIdx.x;
    if (t >= nthreads) return;

    // --- front-load 8 independent LDG.128 (4 rows x 32B) ---
    const float4* xp = x4 + (size_t)t * (2 * ROWS_PER_THREAD);
    float4 a0 = xp[0], a1 = xp[1];
    float4 b0 = xp[2], b1 = xp[3];
    float4 c0 = xp[4], c1v = xp[5];
    float4 d0 = xp[6], d1 = xp[7];

    // --- rotation scalars via MUFU intrinsics (uniform) ---
    float Sr = __ldg(wre + 0) + __ldg(wre + 1) + __ldg(wre + 2);
    float Si = __ldg(wim + 0) + __ldg(wim + 1) + __ldg(wim + 2);
    float e  = __expf(Si);
    float ei = __expf(-Si);
    float K0 = 0.25f * (e + ei);    // 0.5*cosh
    float K3 = -0.25f * (e - ei);   // -0.5*sinh
    float K1 = 0.5f * __cosf(Sr);
    float K2 = -0.5f * __sinf(Sr);

    float4 r;
    r.x = row_result(a0, a1, K0, K1, K2, K3);
    r.y = row_result(b0, b1, K0, K1, K2, K3);
    r.z = row_result(c0, c1v, K0, K1, K2, K3);
    r.w = row_result(d0, d1, K0, K1, K2, K3);

    out4[t] = r;
}

extern "C" void kernel_launch(void* const* d_in, const int* in_sizes, int n_in,
                              void* d_out, int out_size)
{
    const float4* x4 = (const float4*)d_in[0];
    const float* wre = (const float*)d_in[1];
    const float* wim = (const float*)d_in[2];
    float4* out4 = (float4*)d_out;

    int batch = in_sizes[0] / 8;                 // 131072
    int nthreads = batch / ROWS_PER_THREAD;      // 32768
    int threads = 128;
    int blocks = (nthreads + threads - 1) / threads;  // 256
    qc_expect_kernel<<<blocks, threads>>>(x4, wre, wim, out4, nthreads);
}

// round 4
// speedup vs baseline: 1.0246x; 1.0246x over previous
#include <cuda_runtime.h>
#include <cstdint>

// Batched 8-qubit circuit expectation, fully closed-form. (math verified R1)
//
//   out = 0.5*cosh(Si) + 0.5*cos(Sr)*Q - 0.5*sin(Sr)*W - 0.5*sinh(Si)*Xim
//   Sr = sum(w_re), Si = sum(w_im)
//   Q   = rsqrt(1+x1^2) * prod27,   prod27 = rsqrt(prod_{q=2..7}(1+x_q^2))
//   tRq = x_q * rsqrt((1+x_q^2)(1+x_q^4))   (q = 0,1)
//   W   = tR0 * tR1
//   Xim = -tR0 * (x1^2 * tR1) * prod27
//
// R4: fuse rsqrt(a)*rsqrt(b) -> rsqrt(a*b): 10 -> 4 MUFU per row.
// 2 rows/thread (MLP=4) at grid 512x128 (~14 warps/SM) — the R2/R3 midpoint.

__device__ __forceinline__ float row_result(float4 v0, float4 v1,
                                            float K0, float K1, float K2, float K3)
{
    float x0 = v0.x, x1 = v0.y;
    float x0s = x0 * x0;
    float x1s = x1 * x1;

    // p27 = prod_{q=2..7} (1 + x_q^2)
    float p2 = fmaf(v0.z, v0.z, 1.0f);
    float p3 = fmaf(v0.w, v0.w, 1.0f);
    float p4 = fmaf(v1.x, v1.x, 1.0f);
    float p5 = fmaf(v1.y, v1.y, 1.0f);
    float p6 = fmaf(v1.z, v1.z, 1.0f);
    float p7 = fmaf(v1.w, v1.w, 1.0f);
    float p27 = ((p2 * p3) * (p4 * p5)) * (p6 * p7);

    float u0 = fmaf(x0, x0, 1.0f);        // 1+x0^2
    float u1 = fmaf(x1, x1, 1.0f);        // 1+x1^2
    float w0 = fmaf(x0s, x0s, 1.0f);      // 1+x0^4
    float w1 = fmaf(x1s, x1s, 1.0f);      // 1+x1^4

    float prod27 = rsqrtf(p27);           // prod c1_{2..7}
    float rc11   = rsqrtf(u1);            // c1_1
    float rt0    = rsqrtf(u0 * w0);       // c1_0*c2_0
    float rt1    = rsqrtf(u1 * w1);       // c1_1*c2_1

    float Q   = rc11 * prod27;
    float tR0 = x0 * rt0;
    float tR1 = x1 * rt1;
    float W   = tR0 * tR1;
    float Xim = -tR0 * (x1s * tR1) * prod27;

    return fmaf(K1, Q, fmaf(K2, W, fmaf(K3, Xim, K0)));
}

__global__ __launch_bounds__(128)
void qc_expect_kernel(const float4* __restrict__ x4,
                      const float* __restrict__ wre,
                      const float* __restrict__ wim,
                      float2* __restrict__ out2)
{
    int t = blockIdx.x * blockDim.x + threadIdx.x;   // 0..65535, exact grid

    // --- front-load 4 independent LDG.128 (2 rows x 32B) ---
    const float4* xp = x4 + (size_t)t * 4;
    float4 a0 = xp[0], a1 = xp[1];
    float4 b0 = xp[2], b1 = xp[3];

    // --- rotation scalars via MUFU intrinsics (uniform) ---
    float Sr = __ldg(wre + 0) + __ldg(wre + 1) + __ldg(wre + 2);
    float Si = __ldg(wim + 0) + __ldg(wim + 1) + __ldg(wim + 2);
    float e  = __expf(Si);
    float ei = __expf(-Si);
    float K0 = 0.25f * (e + ei);    // 0.5*cosh
    float K3 = -0.25f * (e - ei);   // -0.5*sinh
    float K1 = 0.5f * __cosf(Sr);
    float K2 = -0.5f * __sinf(Sr);

    float2 r;
    r.x = row_result(a0, a1, K0, K1, K2, K3);
    r.y = row_result(b0, b1, K0, K1, K2, K3);
    out2[t] = r;
}

extern "C" void kernel_launch(void* const* d_in, const int* in_sizes, int n_in,
                              void* d_out, int out_size)
{
    const float4* x4 = (const float4*)d_in[0];
    const float* wre = (const float*)d_in[1];
    const float* wim = (const float*)d_in[2];
    float2* out2 = (float2*)d_out;

    int batch = in_sizes[0] / 8;        // 131072
    int nthreads = batch / 2;           // 65536
    int threads = 128;
    int blocks = nthreads / threads;    // 512 (exact)
    qc_expect_kernel<<<blocks, threads>>>(x4, wre, wim, out2);
}

// round 6
// speedup vs baseline: 1.0777x; 1.0518x over previous
#include <cuda_runtime.h>
#include <cstdint>

// Batched 8-qubit circuit expectation, fully closed-form. (math verified R1-R4)
//
//   out = 0.5*cosh(Si) + 0.5*cos(Sr)*Q - 0.5*sin(Sr)*W - 0.5*sinh(Si)*Xim
//   Sr = sum(w_re), Si = sum(w_im)
//   prod27 = rsqrt(prod_{q=2..7}(1+x_q^2))
//   Q   = rsqrt(1+x1^2) * prod27
//   tRq = x_q * rsqrt((1+x_q^2)(1+x_q^4))   (q = 0,1)
//   W   = tR0 * tR1
//   Xim = -tR0 * (x1^2 * tR1) * prod27
//
// R6 (= R5 resubmit after infra failure): best-bench config (1 row/thread,
// 131072 threads, block=256, exact grid) + fused-MUFU math (4 RSQ/row).
// All global loads (row + weights) issued before any arithmetic.

__global__ __launch_bounds__(256)
void qc_expect_kernel(const float4* __restrict__ x4,
                      const float* __restrict__ wre,
                      const float* __restrict__ wim,
                      float* __restrict__ out)
{
    int b = blockIdx.x * (int)blockDim.x + (int)threadIdx.x;  // exact: 131072 threads

    // --- front-load everything: row (2x LDG.128) + 6 uniform weight scalars ---
    const float4* xp = x4 + (size_t)b * 2;
    float4 v0 = xp[0];
    float4 v1 = xp[1];
    float wr0 = __ldg(wre + 0), wr1 = __ldg(wre + 1), wr2 = __ldg(wre + 2);
    float wi0 = __ldg(wim + 0), wi1 = __ldg(wim + 1), wi2 = __ldg(wim + 2);

    // --- rotation scalars via MUFU intrinsics (uniform across threads) ---
    float Sr = wr0 + wr1 + wr2;
    float Si = wi0 + wi1 + wi2;
    float e  = __expf(Si);
    float ei = __expf(-Si);
    float K0 = 0.25f * (e + ei);    // 0.5*cosh(Si)
    float K3 = -0.25f * (e - ei);   // -0.5*sinh(Si)
    float K1 = 0.5f * __cosf(Sr);
    float K2 = -0.5f * __sinf(Sr);

    float x0 = v0.x, x1 = v0.y;
    float x0s = x0 * x0;
    float x1s = x1 * x1;

    // p27 = prod_{q=2..7} (1 + x_q^2)
    float p2 = fmaf(v0.z, v0.z, 1.0f);
    float p3 = fmaf(v0.w, v0.w, 1.0f);
    float p4 = fmaf(v1.x, v1.x, 1.0f);
    float p5 = fmaf(v1.y, v1.y, 1.0f);
    float p6 = fmaf(v1.z, v1.z, 1.0f);
    float p7 = fmaf(v1.w, v1.w, 1.0f);
    float p27 = ((p2 * p3) * (p4 * p5)) * (p6 * p7);

    float u0 = fmaf(x0, x0, 1.0f);        // 1+x0^2
    float u1 = fmaf(x1, x1, 1.0f);        // 1+x1^2
    float w0 = fmaf(x0s, x0s, 1.0f);      // 1+x0^4
    float w1 = fmaf(x1s, x1s, 1.0f);      // 1+x1^4

    float prod27 = rsqrtf(p27);           // prod c1_{2..7}
    float rc11   = rsqrtf(u1);            // c1_1
    float rt0    = rsqrtf(u0 * w0);       // c1_0*c2_0
    float rt1    = rsqrtf(u1 * w1);       // c1_1*c2_1

    float Q   = rc11 * prod27;
    float tR0 = x0 * rt0;
    float tR1 = x1 * rt1;
    float W   = tR0 * tR1;
    float Xim = -tR0 * (x1s * tR1) * prod27;

    out[b] = fmaf(K1, Q, fmaf(K2, W, fmaf(K3, Xim, K0)));
}

extern "C" void kernel_launch(void* const* d_in, const int* in_sizes, int n_in,
                              void* d_out, int out_size)
{
    const float4* x4 = (const float4*)d_in[0];
    const float* wre = (const float*)d_in[1];
    const float* wim = (const float*)d_in[2];
    float* out = (float*)d_out;

    int batch = in_sizes[0] / 8;        // 131072
    int threads = 256;
    int blocks = batch / threads;       // 512 (exact)
    qc_expect_kernel<<<blocks, threads>>>(x4, wre, wim, out);
}